// round 6
// baseline (speedup 1.0000x reference)
#include <cuda_runtime.h>
#include <math.h>

#define N_LEVELS      16
#define HASHMAP_SIZE  (1u << 19)
#define HASH_MASK     (HASHMAP_SIZE - 1u)
#define P2            2654435761u
#define P3            805459861u

struct LvlTable {
    float    fres[N_LEVELS];
    unsigned r1[N_LEVELS];
    unsigned r1sq[N_LEVELS];
    unsigned dense_mask;
};

// 8 lanes per point (one corner each), 4 points per warp.
// Levels processed in 2 rounds of 8; 3-stage transpose-reduce leaves the
// complete sum of level (base + c) in lane c.
__global__ void __launch_bounds__(256)
hashenc_kernel(const float* __restrict__ pos,
               const float* __restrict__ emb,
               float* __restrict__ out,
               LvlTable lt,
               int n_points)
{
    const int tid    = blockIdx.x * blockDim.x + threadIdx.x;
    const int lane   = threadIdx.x & 31;
    const int c      = lane & 7;        // corner id: (i<<2)|(j<<1)|k
    const int sub    = lane >> 3;       // point slot within warp (0..3)
    const int p      = (tid >> 5) * 4 + sub;

    const bool valid = (p < n_points);
    const int  pp    = valid ? p : 0;

    const unsigned bi = (c >> 2) & 1;
    const unsigned bj = (c >> 1) & 1;
    const unsigned bk =  c       & 1;

    const float px = pos[pp * 3 + 0];
    const float py = pos[pp * 3 + 1];
    const float pz = pos[pp * 3 + 2];

    float2* __restrict__ o2 = reinterpret_cast<float2*>(out);

#pragma unroll
    for (int round = 0; round < 2; ++round) {
        float a[8], b[8];   // weighted corner feats for 8 levels

#pragma unroll
        for (int j = 0; j < 8; ++j) {
            const int l = round * 8 + j;
            const float fres = lt.fres[l];

            const float sx = px * fres, sy = py * fres, sz = pz * fres;
            const float fx = floorf(sx), fy = floorf(sy), fz = floorf(sz);
            const float wx = sx - fx,   wy = sy - fy,   wz = sz - fz;

            const unsigned ux = (unsigned)(int)fx + bi;
            const unsigned uy = (unsigned)(int)fy + bj;
            const unsigned uz = (unsigned)(int)fz + bk;

            unsigned idx;
            if ((lt.dense_mask >> l) & 1u) {
                idx = ux * lt.r1sq[l] + uy * lt.r1[l] + uz;
            } else {
                idx = (ux ^ (uy * P2) ^ (uz * P3)) & HASH_MASK;
            }

            const float2* __restrict__ table =
                reinterpret_cast<const float2*>(emb) + (size_t)l * HASHMAP_SIZE;
            const float2 f = __ldg(&table[idx]);

            const float ax = bi ? wx : (1.0f - wx);
            const float ay = bj ? wy : (1.0f - wy);
            const float az = bk ? wz : (1.0f - wz);
            const float w  = ax * ay * az;

            a[j] = f.x * w;
            b[j] = f.y * w;
        }

        // ---- 3-stage transpose reduce across the 8 corner lanes ----
        // stage o=4: keep levels with bit2 == lane bit2
        float a4[4], b4[4];
        const bool h4 = (c & 4) != 0;
#pragma unroll
        for (int j = 0; j < 4; ++j) {
            float sendA = h4 ? a[j] : a[j + 4];
            float keepA = h4 ? a[j + 4] : a[j];
            a4[j] = keepA + __shfl_xor_sync(0xffffffffu, sendA, 4);
            float sendB = h4 ? b[j] : b[j + 4];
            float keepB = h4 ? b[j + 4] : b[j];
            b4[j] = keepB + __shfl_xor_sync(0xffffffffu, sendB, 4);
        }
        // stage o=2
        float a2[2], b2[2];
        const bool h2 = (c & 2) != 0;
#pragma unroll
        for (int j = 0; j < 2; ++j) {
            float sendA = h2 ? a4[j] : a4[j + 2];
            float keepA = h2 ? a4[j + 2] : a4[j];
            a2[j] = keepA + __shfl_xor_sync(0xffffffffu, sendA, 2);
            float sendB = h2 ? b4[j] : b4[j + 2];
            float keepB = h2 ? b4[j + 2] : b4[j];
            b2[j] = keepB + __shfl_xor_sync(0xffffffffu, sendB, 2);
        }
        // stage o=1
        const bool h1 = (c & 1) != 0;
        float sendA = h1 ? a2[0] : a2[1];
        float keepA = h1 ? a2[1] : a2[0];
        const float r0 = keepA + __shfl_xor_sync(0xffffffffu, sendA, 1);
        float sendB = h1 ? b2[0] : b2[1];
        float keepB = h1 ? b2[1] : b2[0];
        const float r1 = keepB + __shfl_xor_sync(0xffffffffu, sendB, 1);

        // lane c now holds the complete result for level round*8 + c
        if (valid) {
            o2[(size_t)p * 16 + round * 8 + c] = make_float2(r0, r1);
        }
    }
}

extern "C" void kernel_launch(void* const* d_in, const int* in_sizes, int n_in,
                              void* d_out, int out_size)
{
    const float* positions  = (const float*)d_in[0];   // [N_POINTS, 3] f32
    const float* embeddings = (const float*)d_in[1];   // [16, 2^19, 2] f32
    float*       out        = (float*)d_out;           // [N_POINTS, 32] f32

    const int n_points = in_sizes[0] / 3;

    // Mirror numpy exactly in double precision (libm exp/log/pow)
    LvlTable lt;
    lt.dense_mask = 0;
    const double scale = exp((log(2048.0) - log(16.0)) / 15.0);
    for (int l = 0; l < N_LEVELS; ++l) {
        const int res = (int)floor(16.0 * pow(scale, (double)l));
        lt.fres[l] = (float)res;
        const unsigned r1 = (unsigned)(res + 1);
        lt.r1[l]   = r1;
        lt.r1sq[l] = r1 * r1;
        if ((long long)r1 * r1 * r1 <= (long long)HASHMAP_SIZE)
            lt.dense_mask |= (1u << l);
    }

    const long long total_threads = (long long)n_points * 8;
    const int threads = 256;
    const int blocks  = (int)((total_threads + threads - 1) / threads);
    hashenc_kernel<<<blocks, threads>>>(positions, embeddings, out, lt, n_points);
}

// round 7
// speedup vs baseline: 1.4957x; 1.4957x over previous
#include <cuda_runtime.h>
#include <math.h>

#define N_LEVELS      16
#define HASHMAP_SIZE  (1u << 19)
#define HASH_MASK     (HASHMAP_SIZE - 1u)
#define P2            2654435761u
#define P3            805459861u

#define KEY_BITS_AXIS 7
#define HISTO_SIZE    (1u << (3 * KEY_BITS_AXIS))   // 2^21 buckets
#define SCAN_BLOCKS   (HISTO_SIZE / 1024)           // 2048
#define MAX_POINTS    2200000

struct ResTable {
    int res[N_LEVELS];
};

// ---- static scratch (no dynamic allocation allowed) ----
__device__ unsigned g_histo[HISTO_SIZE];     // 8 MB: counts -> exclusive offsets -> cursors
__device__ unsigned g_bsum[SCAN_BLOCKS];     // block totals for the scan
__device__ unsigned g_keys[MAX_POINTS];      // per-point morton key
__device__ float4   g_spos[MAX_POINTS];      // sorted (x, y, z, orig_idx)

// ---------------- sort pre-pass ----------------

__device__ __forceinline__ unsigned part1by2(unsigned x) {
    x &= 0x3ff;
    x = (x | (x << 16)) & 0x030000FF;
    x = (x | (x << 8))  & 0x0300F00F;
    x = (x | (x << 4))  & 0x030C30C3;
    x = (x | (x << 2))  & 0x09249249;
    return x;
}

__global__ void k_key_histo(const float* __restrict__ pos, int n) {
    int i = blockIdx.x * blockDim.x + threadIdx.x;
    if (i >= n) return;
    const float x = pos[i * 3 + 0];
    const float y = pos[i * 3 + 1];
    const float z = pos[i * 3 + 2];
    const int R = 1 << KEY_BITS_AXIS;
    unsigned kx = min(R - 1, max(0, (int)(x * (float)R)));
    unsigned ky = min(R - 1, max(0, (int)(y * (float)R)));
    unsigned kz = min(R - 1, max(0, (int)(z * (float)R)));
    unsigned key = part1by2(kx) | (part1by2(ky) << 1) | (part1by2(kz) << 2);
    g_keys[i] = key;
    atomicAdd(&g_histo[key], 1u);
}

__global__ void k_scan1() {   // per-1024-block exclusive scan of g_histo
    __shared__ unsigned s[1024];
    const unsigned t = threadIdx.x;
    const unsigned i = blockIdx.x * 1024 + t;
    const unsigned v = g_histo[i];
    s[t] = v;
    __syncthreads();
    for (int o = 1; o < 1024; o <<= 1) {
        unsigned add = (t >= (unsigned)o) ? s[t - o] : 0u;
        __syncthreads();
        s[t] += add;
        __syncthreads();
    }
    g_histo[i] = s[t] - v;                 // exclusive within block
    if (t == 1023) g_bsum[blockIdx.x] = s[t];
}

__global__ void k_scan2() {   // 1 block x 1024 threads scans 2048 block totals
    __shared__ unsigned s[1024];
    const unsigned t = threadIdx.x;
    const unsigned a = g_bsum[2 * t];
    const unsigned b = g_bsum[2 * t + 1];
    const unsigned sum = a + b;
    s[t] = sum;
    __syncthreads();
    for (int o = 1; o < 1024; o <<= 1) {
        unsigned add = (t >= (unsigned)o) ? s[t - o] : 0u;
        __syncthreads();
        s[t] += add;
        __syncthreads();
    }
    const unsigned excl = s[t] - sum;
    g_bsum[2 * t]     = excl;
    g_bsum[2 * t + 1] = excl + a;
}

__global__ void k_addback() {
    g_histo[blockIdx.x * 1024 + threadIdx.x] += g_bsum[blockIdx.x];
}

__global__ void k_scatter(const float* __restrict__ pos, int n) {
    int i = blockIdx.x * blockDim.x + threadIdx.x;
    if (i >= n) return;
    const unsigned key = g_keys[i];
    const unsigned dst = atomicAdd(&g_histo[key], 1u);
    g_spos[dst] = make_float4(pos[i * 3 + 0], pos[i * 3 + 1], pos[i * 3 + 2],
                              __int_as_float(i));
}

// ---------------- main encode (R5 body, sorted input) ----------------

__global__ void __launch_bounds__(256)
hashenc_kernel(const float* __restrict__ emb,
               float* __restrict__ out,
               ResTable rt,
               int n_points)
{
    const int tid   = blockIdx.x * blockDim.x + threadIdx.x;
    const int lane  = threadIdx.x & 31;
    const int c     = lane & 7;        // corner id: (i<<2)|(j<<1)|k
    const int sub   = lane >> 3;       // point slot within warp (0..3)
    const int pslot = (tid >> 5) * 4 + sub;

    const bool valid = (pslot < n_points);
    const int  ps    = valid ? pslot : 0;

    const unsigned bi = (c >> 2) & 1;
    const unsigned bj = (c >> 1) & 1;
    const unsigned bk =  c       & 1;

    const float4 sp = __ldg(&g_spos[ps]);
    const float px = sp.x, py = sp.y, pz = sp.z;
    const int orig = __float_as_int(sp.w);

    float acc0 = 0.f, acc1 = 0.f, acc2 = 0.f, acc3 = 0.f;

#pragma unroll
    for (int l = 0; l < N_LEVELS; ++l) {
        const int   res  = rt.res[l];
        const float fres = (float)res;

        const float sx = px * fres, sy = py * fres, sz = pz * fres;
        const float fx = floorf(sx), fy = floorf(sy), fz = floorf(sz);
        const float wx = sx - fx,   wy = sy - fy,   wz = sz - fz;

        const unsigned ux = (unsigned)(int)fx + bi;
        const unsigned uy = (unsigned)(int)fy + bj;
        const unsigned uz = (unsigned)(int)fz + bk;

        const unsigned r1 = (unsigned)(res + 1);
        const bool dense =
            ((long long)r1 * (long long)r1 * (long long)r1) <= (long long)HASHMAP_SIZE;

        unsigned idx;
        if (dense) {
            idx = ux * (r1 * r1) + uy * r1 + uz;
        } else {
            idx = (ux ^ (uy * P2) ^ (uz * P3)) & HASH_MASK;
        }

        const float2* __restrict__ table =
            reinterpret_cast<const float2*>(emb) + (size_t)l * HASHMAP_SIZE;
        const float2 f = __ldg(&table[idx]);

        const float ax = bi ? wx : (1.0f - wx);
        const float ay = bj ? wy : (1.0f - wy);
        const float az = bk ? wz : (1.0f - wz);
        const float w  = ax * ay * az;

        float v0 = f.x * w;
        float v1 = f.y * w;

        v0 += __shfl_xor_sync(0xffffffffu, v0, 4);
        v1 += __shfl_xor_sync(0xffffffffu, v1, 4);
        v0 += __shfl_xor_sync(0xffffffffu, v0, 2);
        v1 += __shfl_xor_sync(0xffffffffu, v1, 2);
        v0 += __shfl_xor_sync(0xffffffffu, v0, 1);
        v1 += __shfl_xor_sync(0xffffffffu, v1, 1);

        if ((l >> 1) == c) {
            if (l & 1) { acc2 = v0; acc3 = v1; }
            else       { acc0 = v0; acc1 = v1; }
        }
    }

    if (valid) {
        float4* __restrict__ o4 = reinterpret_cast<float4*>(out);
        o4[(size_t)orig * 8 + c] = make_float4(acc0, acc1, acc2, acc3);
    }
}

extern "C" void kernel_launch(void* const* d_in, const int* in_sizes, int n_in,
                              void* d_out, int out_size)
{
    const float* positions  = (const float*)d_in[0];   // [N_POINTS, 3] f32
    const float* embeddings = (const float*)d_in[1];   // [16, 2^19, 2] f32
    float*       out        = (float*)d_out;           // [N_POINTS, 32] f32

    const int n_points = in_sizes[0] / 3;

    ResTable rt;
    const double scale = exp((log(2048.0) - log(16.0)) / 15.0);
    for (int l = 0; l < N_LEVELS; ++l) {
        rt.res[l] = (int)floor(16.0 * pow(scale, (double)l));
    }

    // ---- sort pre-pass ----
    void* histo_ptr = nullptr;
    cudaGetSymbolAddress(&histo_ptr, g_histo);
    cudaMemsetAsync(histo_ptr, 0, HISTO_SIZE * sizeof(unsigned));

    const int pblocks = (n_points + 255) / 256;
    k_key_histo<<<pblocks, 256>>>(positions, n_points);
    k_scan1<<<SCAN_BLOCKS, 1024>>>();
    k_scan2<<<1, 1024>>>();
    k_addback<<<SCAN_BLOCKS, 1024>>>();
    k_scatter<<<pblocks, 256>>>(positions, n_points);

    // ---- main encode: 8 threads per point ----
    const long long total_threads = (long long)n_points * 8;
    const int threads = 256;
    const int blocks  = (int)((total_threads + threads - 1) / threads);
    hashenc_kernel<<<blocks, threads>>>(embeddings, out, rt, n_points);
}